// round 6
// baseline (speedup 1.0000x reference)
#include <cuda_runtime.h>
#include <cstdint>

// LightGCN aggregation (COO SpMM, DIM=32):
//   out[r] = sum_{e: rows[e]==r} vals[e] * x[cols[e]]
//
// Two-phase: counting-sort edges by row (hist -> scan -> scatter), then a
// CSR-style segment reduce with register accumulation and ONE coalesced
// 128B store per row. Eliminates the 205MB RED-scatter L2 write traffic and
// all 12.8M atomic lanes that bound the one-pass version at ~39us.
//
// R5 fix: csr_spmm launch used warps*8 threads instead of warps*32 ->
// 3/4 of rows never computed (rel_err 0.866 = sqrt(0.75)).

static constexpr int DIM  = 32;
static constexpr int QPE  = DIM / 4;
static constexpr int MAXN = 131072;    // > 100,000 nodes
static constexpr int MAXE = 1700000;   // > 1,600,000 edges
static constexpr int TPB  = 256;
static constexpr int SCAN_T = 1024;

// ---- scratch (static device globals; no runtime allocation) ----
__device__ int                d_count[MAXN];
__device__ int                d_start[MAXN + 1];
__device__ int                d_cursor[MAXN];
__device__ unsigned long long d_edges[MAXE];   // hi32 = val bits, lo32 = col

// ============================ phase 1: histogram ============================
__global__ void __launch_bounds__(TPB)
hist_kernel(const int4* __restrict__ rows4, int n_edges)
{
    int idx = blockIdx.x * TPB + threadIdx.x;
    int ng  = n_edges >> 2;
    if (idx < ng) {
        int4 r = __ldg(&rows4[idx]);
        atomicAdd(&d_count[r.x], 1);
        atomicAdd(&d_count[r.y], 1);
        atomicAdd(&d_count[r.z], 1);
        atomicAdd(&d_count[r.w], 1);
    } else if (idx == ng) {                  // scalar tail (n_edges % 4)
        const int* rows = (const int*)rows4;
        for (int e = ng * 4; e < n_edges; e++)
            atomicAdd(&d_count[rows[e]], 1);
    }
}

// ============================ phase 2: scan =================================
// Single-block exclusive scan of d_count -> d_start (+ d_cursor copy).
__global__ void __launch_bounds__(SCAN_T)
scan_kernel(int n_nodes)
{
    __shared__ int buf[SCAN_T];
    int t   = threadIdx.x;
    int per = (n_nodes + SCAN_T - 1) / SCAN_T;
    int lo  = t * per;
    int hi  = min(lo + per, n_nodes);

    int sum = 0;
    for (int i = lo; i < hi; i++) sum += d_count[i];
    buf[t] = sum;
    __syncthreads();

    // Kogge-Stone inclusive scan over the 1024 partials
    #pragma unroll
    for (int off = 1; off < SCAN_T; off <<= 1) {
        int add = (t >= off) ? buf[t - off] : 0;
        __syncthreads();
        buf[t] += add;
        __syncthreads();
    }

    int running = (t == 0) ? 0 : buf[t - 1];
    for (int i = lo; i < hi; i++) {
        int c = d_count[i];
        d_start[i]  = running;
        d_cursor[i] = running;
        running += c;
    }
    if (hi == n_nodes && lo < n_nodes) d_start[n_nodes] = running;
    if (n_nodes == 0 && t == 0)        d_start[0] = 0;
}

// ============================ phase 3: scatter ==============================
__global__ void __launch_bounds__(TPB)
scatter_kernel(const int4*   __restrict__ rows4,
               const int4*   __restrict__ cols4,
               const float4* __restrict__ vals4,
               int n_edges)
{
    int idx = blockIdx.x * TPB + threadIdx.x;
    int ng  = n_edges >> 2;
    if (idx < ng) {
        int4   r = __ldg(&rows4[idx]);
        int4   c = __ldg(&cols4[idx]);
        float4 v = __ldg(&vals4[idx]);

        int ra[4] = { r.x, r.y, r.z, r.w };
        int ca[4] = { c.x, c.y, c.z, c.w };
        float va[4] = { v.x, v.y, v.z, v.w };
        #pragma unroll
        for (int i = 0; i < 4; i++) {
            int pos = atomicAdd(&d_cursor[ra[i]], 1);
            d_edges[pos] = ((unsigned long long)__float_as_uint(va[i]) << 32)
                           | (unsigned int)ca[i];
        }
    } else if (idx == ng) {
        const int*   rows = (const int*)  rows4;
        const int*   cols = (const int*)  cols4;
        const float* vals = (const float*)vals4;
        for (int e = ng * 4; e < n_edges; e++) {
            int pos = atomicAdd(&d_cursor[rows[e]], 1);
            d_edges[pos] = ((unsigned long long)__float_as_uint(vals[e]) << 32)
                           | (unsigned int)cols[e];
        }
    }
}

// ============================ phase 4: CSR SpMM =============================
// warp = 4 consecutive rows; octet (8 lanes) per row; lane q holds quarter q.
// Sequential edge reads for a row hit the same 128B L1 line 16x; gather of
// x[col] is one contiguous 128B segment across the octet; single STG.128
// per lane (warp writes 4 rows = 512B contiguous).
__global__ void __launch_bounds__(TPB)
csr_spmm_kernel(const float4* __restrict__ x4,   // [n_nodes * 8]
                float4*       __restrict__ out4, // [n_nodes * 8]
                int n_nodes)
{
    int tid  = blockIdx.x * TPB + threadIdx.x;
    int warp = tid >> 5;
    int lane = threadIdx.x & 31;
    int q    = lane & 7;
    int sub  = lane >> 3;

    int row = warp * 4 + sub;
    if (row >= n_nodes) return;

    int s = __ldg(&d_start[row]);
    int e = __ldg(&d_start[row + 1]);

    float4 acc = make_float4(0.f, 0.f, 0.f, 0.f);

    int i = s;
    for (; i + 1 < e; i += 2) {
        unsigned long long p0 = __ldg(&d_edges[i]);
        unsigned long long p1 = __ldg(&d_edges[i + 1]);
        int   c0 = (int)(unsigned int)p0;
        int   c1 = (int)(unsigned int)p1;
        float v0 = __uint_as_float((unsigned int)(p0 >> 32));
        float v1 = __uint_as_float((unsigned int)(p1 >> 32));
        float4 xv0 = __ldg(&x4[c0 * QPE + q]);
        float4 xv1 = __ldg(&x4[c1 * QPE + q]);
        acc.x += v0 * xv0.x;  acc.y += v0 * xv0.y;
        acc.z += v0 * xv0.z;  acc.w += v0 * xv0.w;
        acc.x += v1 * xv1.x;  acc.y += v1 * xv1.y;
        acc.z += v1 * xv1.z;  acc.w += v1 * xv1.w;
    }
    if (i < e) {
        unsigned long long p = __ldg(&d_edges[i]);
        int   c = (int)(unsigned int)p;
        float v = __uint_as_float((unsigned int)(p >> 32));
        float4 xv = __ldg(&x4[c * QPE + q]);
        acc.x += v * xv.x;  acc.y += v * xv.y;
        acc.z += v * xv.z;  acc.w += v * xv.w;
    }

    out4[row * QPE + q] = acc;
}

// ===================== fallback: one-pass RED (oversize) ====================
__device__ __forceinline__ void red_add_v4(float* dst, float4 m) {
    asm volatile("red.global.add.v4.f32 [%0], {%1, %2, %3, %4};"
                 :: "l"(dst), "f"(m.x), "f"(m.y), "f"(m.z), "f"(m.w) : "memory");
}

__global__ void __launch_bounds__(TPB)
coo_red_kernel(const int* __restrict__ rows, const int* __restrict__ cols,
               const float* __restrict__ vals, const float4* __restrict__ x4,
               float* __restrict__ out, int n_edges)
{
    int idx = blockIdx.x * TPB + threadIdx.x;
    if (idx >= n_edges * QPE) return;
    int e = idx >> 3, q = idx & 7;
    int   r = rows[e], c = cols[e];
    float v = vals[e];
    float4 xv = __ldg(&x4[c * QPE + q]);
    float4 m = make_float4(xv.x * v, xv.y * v, xv.z * v, xv.w * v);
    red_add_v4(out + ((size_t)r * DIM + q * 4), m);
}

// ================================ launch ====================================
extern "C" void kernel_launch(void* const* d_in, const int* in_sizes, int n_in,
                              void* d_out, int out_size)
{
    const int*    rows = (const int*)   d_in[0];
    const int*    cols = (const int*)   d_in[1];
    const float*  vals = (const float*) d_in[2];
    const float4* x4   = (const float4*)d_in[3];

    int n_edges = in_sizes[0];
    int n_nodes = out_size / DIM;

    if (n_nodes > MAXN || n_edges > MAXE) {
        // oversize safety net: one-pass RED kernel
        cudaMemsetAsync(d_out, 0, (size_t)out_size * sizeof(float), 0);
        int total = n_edges * QPE;
        coo_red_kernel<<<(total + TPB - 1) / TPB, TPB>>>(
            rows, cols, vals, x4, (float*)d_out, n_edges);
        return;
    }

    int* count_ptr = nullptr;
    cudaGetSymbolAddress((void**)&count_ptr, d_count);
    cudaMemsetAsync(count_ptr, 0, (size_t)n_nodes * sizeof(int), 0);

    int ng        = n_edges >> 2;
    int e_threads = ng + 1;                       // +1 thread handles tail
    int e_blocks  = (e_threads + TPB - 1) / TPB;

    hist_kernel<<<e_blocks, TPB>>>((const int4*)rows, n_edges);
    scan_kernel<<<1, SCAN_T>>>(n_nodes);
    scatter_kernel<<<e_blocks, TPB>>>((const int4*)rows, (const int4*)cols,
                                      (const float4*)vals, n_edges);

    // one warp (32 threads) per 4 rows  -->  n_warps * 32 threads
    int n_warps   = (n_nodes + 3) / 4;
    int n_threads = n_warps * 32;                 // FIXED (was *8)
    int n_blocks  = (n_threads + TPB - 1) / TPB;
    csr_spmm_kernel<<<n_blocks, TPB>>>(x4, (float4*)d_out, n_nodes);
}

// round 7
// speedup vs baseline: 3.0597x; 3.0597x over previous
#include <cuda_runtime.h>
#include <cstdint>

// LightGCN aggregation (COO SpMM, DIM=32):
//   out[r] = sum_{e: rows[e]==r} vals[e] * x[cols[e]]
//
// Two-phase: counting-sort edges by row, then CSR segment-reduce with
// register accumulation (no atomics on the 12.8MB output).
//
// R6 lesson: single-block scan with serial per-thread loops cost ~190us.
// Replaced with a 3-pass parallel blocked scan (~4us total).
// csr_spmm upgraded to warp-per-row with 4-way edge MLP + shfl reduce.

static constexpr int DIM  = 32;
static constexpr int QPE  = DIM / 4;
static constexpr int MAXN = 131072;     // > 100,000 nodes
static constexpr int MAXE = 1700000;    // > 1,600,000 edges
static constexpr int TPB  = 256;
static constexpr int SCAN_CHUNK = 1024; // counts per scan-A block
static constexpr int MAXB = (MAXN + SCAN_CHUNK - 1) / SCAN_CHUNK; // 128

// ---- scratch (static device globals; no runtime allocation) ----
__device__ int                d_count[MAXN];
__device__ int                d_start[MAXN + 1];
__device__ int                d_cursor[MAXN];
__device__ int                d_bsum[MAXB];
__device__ int                d_total;
__device__ unsigned long long d_edges[MAXE];   // hi32 = val bits, lo32 = col

// ============================ phase 1: histogram ============================
__global__ void __launch_bounds__(TPB)
hist_kernel(const int4* __restrict__ rows4, int n_edges)
{
    int idx = blockIdx.x * TPB + threadIdx.x;
    int ng  = n_edges >> 2;
    if (idx < ng) {
        int4 r = __ldg(&rows4[idx]);
        atomicAdd(&d_count[r.x], 1);
        atomicAdd(&d_count[r.y], 1);
        atomicAdd(&d_count[r.z], 1);
        atomicAdd(&d_count[r.w], 1);
    } else if (idx == ng) {                  // scalar tail (n_edges % 4)
        const int* rows = (const int*)rows4;
        for (int e = ng * 4; e < n_edges; e++)
            atomicAdd(&d_count[rows[e]], 1);
    }
}

// ===================== phase 2a: per-block local scan =======================
// Each block: 256 threads x 4 counts = 1024. Writes the LOCAL exclusive scan
// into d_start and the block total into d_bsum[blockIdx.x].
__global__ void __launch_bounds__(TPB)
scanA_kernel(int n_nodes)
{
    __shared__ int warp_sums[8];
    __shared__ int warp_off[8];

    int t    = threadIdx.x;
    int lane = t & 31;
    int wid  = t >> 5;
    int base = blockIdx.x * SCAN_CHUNK + t * 4;

    int c0 = (base + 0 < n_nodes) ? d_count[base + 0] : 0;
    int c1 = (base + 1 < n_nodes) ? d_count[base + 1] : 0;
    int c2 = (base + 2 < n_nodes) ? d_count[base + 2] : 0;
    int c3 = (base + 3 < n_nodes) ? d_count[base + 3] : 0;
    int tsum = c0 + c1 + c2 + c3;

    // inclusive warp scan of per-thread sums
    int v = tsum;
    #pragma unroll
    for (int off = 1; off < 32; off <<= 1) {
        int n = __shfl_up_sync(0xffffffffu, v, off);
        if (lane >= off) v += n;
    }
    if (lane == 31) warp_sums[wid] = v;
    __syncthreads();

    if (t == 0) {
        int run = 0;
        #pragma unroll
        for (int w = 0; w < 8; w++) {
            warp_off[w] = run;
            run += warp_sums[w];
        }
        d_bsum[blockIdx.x] = run;      // block total
    }
    __syncthreads();

    int excl = (v - tsum) + warp_off[wid];   // exclusive offset of this thread
    if (base + 0 < n_nodes) d_start[base + 0] = excl;
    if (base + 1 < n_nodes) d_start[base + 1] = excl + c0;
    if (base + 2 < n_nodes) d_start[base + 2] = excl + c0 + c1;
    if (base + 3 < n_nodes) d_start[base + 3] = excl + c0 + c1 + c2;
}

// ===================== phase 2b: scan the block sums ========================
// One block; parallel Kogge-Stone over <=MAXB block sums in smem.
__global__ void __launch_bounds__(MAXB)
scanB_kernel(int n_blocks)
{
    __shared__ int buf[MAXB];
    int t = threadIdx.x;
    int x = (t < n_blocks) ? d_bsum[t] : 0;
    buf[t] = x;
    __syncthreads();

    #pragma unroll
    for (int off = 1; off < MAXB; off <<= 1) {
        int add = (t >= off) ? buf[t - off] : 0;
        __syncthreads();
        buf[t] += add;
        __syncthreads();
    }

    if (t < n_blocks) d_bsum[t] = buf[t] - x;   // exclusive
    if (t == MAXB - 1) d_total = buf[MAXB - 1];
}

// ===================== phase 2c: add offsets, init cursors ==================
__global__ void __launch_bounds__(TPB)
scanC_kernel(int n_nodes)
{
    int t    = threadIdx.x;
    int off  = d_bsum[blockIdx.x];
    int base = blockIdx.x * SCAN_CHUNK + t * 4;

    #pragma unroll
    for (int k = 0; k < 4; k++) {
        int i = base + k;
        if (i < n_nodes) {
            int s = d_start[i] + off;
            d_start[i]  = s;
            d_cursor[i] = s;
        }
    }
    if (blockIdx.x == 0 && t == 0) d_start[n_nodes] = d_total;
}

// ============================ phase 3: scatter ==============================
__global__ void __launch_bounds__(TPB)
scatter_kernel(const int4*   __restrict__ rows4,
               const int4*   __restrict__ cols4,
               const float4* __restrict__ vals4,
               int n_edges)
{
    int idx = blockIdx.x * TPB + threadIdx.x;
    int ng  = n_edges >> 2;
    if (idx < ng) {
        int4   r = __ldg(&rows4[idx]);
        int4   c = __ldg(&cols4[idx]);
        float4 v = __ldg(&vals4[idx]);

        int ra[4] = { r.x, r.y, r.z, r.w };
        int ca[4] = { c.x, c.y, c.z, c.w };
        float va[4] = { v.x, v.y, v.z, v.w };
        #pragma unroll
        for (int i = 0; i < 4; i++) {
            int pos = atomicAdd(&d_cursor[ra[i]], 1);
            d_edges[pos] = ((unsigned long long)__float_as_uint(va[i]) << 32)
                           | (unsigned int)ca[i];
        }
    } else if (idx == ng) {
        const int*   rows = (const int*)  rows4;
        const int*   cols = (const int*)  cols4;
        const float* vals = (const float*)vals4;
        for (int e = ng * 4; e < n_edges; e++) {
            int pos = atomicAdd(&d_cursor[rows[e]], 1);
            d_edges[pos] = ((unsigned long long)__float_as_uint(vals[e]) << 32)
                           | (unsigned int)cols[e];
        }
    }
}

// ============================ phase 4: CSR SpMM =============================
// warp = 1 row. lane: q = lane&7 (float4 quarter), j = lane>>3 (0..3).
// The 4 j-groups process edges s+j, s+j+4, ... concurrently: 4 consecutive
// 8B edge packets per iteration (one 32B sector, broadcast across q-lanes),
// 4 independent gather chains in flight. Cross-group reduce via shfl_xor
// (8, 16), then lanes 0..7 store one coalesced 128B row.
__global__ void __launch_bounds__(TPB)
csr_spmm_kernel(const float4* __restrict__ x4,   // [n_nodes * 8]
                float4*       __restrict__ out4, // [n_nodes * 8]
                int n_nodes)
{
    int tid  = blockIdx.x * TPB + threadIdx.x;
    int row  = tid >> 5;
    int lane = threadIdx.x & 31;
    int q    = lane & 7;
    int j    = lane >> 3;

    if (row >= n_nodes) return;

    int s = __ldg(&d_start[row]);
    int e = __ldg(&d_start[row + 1]);

    float4 acc = make_float4(0.f, 0.f, 0.f, 0.f);

    for (int i = s + j; i < e; i += 4) {
        unsigned long long p = __ldg(&d_edges[i]);
        int   c = (int)(unsigned int)p;
        float v = __uint_as_float((unsigned int)(p >> 32));
        float4 xv = __ldg(&x4[c * QPE + q]);
        acc.x += v * xv.x;
        acc.y += v * xv.y;
        acc.z += v * xv.z;
        acc.w += v * xv.w;
    }

    // reduce across the 4 j-groups (lanes q, q+8, q+16, q+24)
    #pragma unroll
    for (int m = 8; m <= 16; m <<= 1) {
        acc.x += __shfl_xor_sync(0xffffffffu, acc.x, m);
        acc.y += __shfl_xor_sync(0xffffffffu, acc.y, m);
        acc.z += __shfl_xor_sync(0xffffffffu, acc.z, m);
        acc.w += __shfl_xor_sync(0xffffffffu, acc.w, m);
    }

    if (j == 0)
        out4[row * QPE + q] = acc;
}

// ===================== fallback: one-pass RED (oversize) ====================
__device__ __forceinline__ void red_add_v4(float* dst, float4 m) {
    asm volatile("red.global.add.v4.f32 [%0], {%1, %2, %3, %4};"
                 :: "l"(dst), "f"(m.x), "f"(m.y), "f"(m.z), "f"(m.w) : "memory");
}

__global__ void __launch_bounds__(TPB)
coo_red_kernel(const int* __restrict__ rows, const int* __restrict__ cols,
               const float* __restrict__ vals, const float4* __restrict__ x4,
               float* __restrict__ out, int n_edges)
{
    int idx = blockIdx.x * TPB + threadIdx.x;
    if (idx >= n_edges * QPE) return;
    int e = idx >> 3, q = idx & 7;
    int   r = rows[e], c = cols[e];
    float v = vals[e];
    float4 xv = __ldg(&x4[c * QPE + q]);
    float4 m = make_float4(xv.x * v, xv.y * v, xv.z * v, xv.w * v);
    red_add_v4(out + ((size_t)r * DIM + q * 4), m);
}

// ================================ launch ====================================
extern "C" void kernel_launch(void* const* d_in, const int* in_sizes, int n_in,
                              void* d_out, int out_size)
{
    const int*    rows = (const int*)   d_in[0];
    const int*    cols = (const int*)   d_in[1];
    const float*  vals = (const float*) d_in[2];
    const float4* x4   = (const float4*)d_in[3];

    int n_edges = in_sizes[0];
    int n_nodes = out_size / DIM;

    if (n_nodes > MAXN || n_edges > MAXE) {
        // oversize safety net: one-pass RED kernel
        cudaMemsetAsync(d_out, 0, (size_t)out_size * sizeof(float), 0);
        int total = n_edges * QPE;
        coo_red_kernel<<<(total + TPB - 1) / TPB, TPB>>>(
            rows, cols, vals, x4, (float*)d_out, n_edges);
        return;
    }

    int* count_ptr = nullptr;
    cudaGetSymbolAddress((void**)&count_ptr, d_count);
    cudaMemsetAsync(count_ptr, 0, (size_t)n_nodes * sizeof(int), 0);

    int ng        = n_edges >> 2;
    int e_threads = ng + 1;                       // +1 thread handles tail
    int e_blocks  = (e_threads + TPB - 1) / TPB;

    int scan_blocks = (n_nodes + SCAN_CHUNK - 1) / SCAN_CHUNK;

    hist_kernel <<<e_blocks, TPB>>>((const int4*)rows, n_edges);
    scanA_kernel<<<scan_blocks, TPB>>>(n_nodes);
    scanB_kernel<<<1, MAXB>>>(scan_blocks);
    scanC_kernel<<<scan_blocks, TPB>>>(n_nodes);
    scatter_kernel<<<e_blocks, TPB>>>((const int4*)rows, (const int4*)cols,
                                      (const float4*)vals, n_edges);

    // one warp (32 threads) per row
    int n_threads = n_nodes * 32;
    int n_blocks  = (n_threads + TPB - 1) / TPB;
    csr_spmm_kernel<<<n_blocks, TPB>>>(x4, (float4*)d_out, n_nodes);
}